// round 1
// baseline (speedup 1.0000x reference)
#include <cuda_runtime.h>

// Fused ModernNet inference: pad(-1) -> conv5x5s2(12) +posbias relu ->
// pad(-1) -> grouped conv5x5s2(12) +posbias relu -> fc192x30 relu -> fc30x10
//
// Layout: 8 samples per 256-thread block, warp-per-sample for compute phases.
// All intermediates live in dynamic shared memory (91.4 KB/block, 2 blocks/SM).

#define SPB 8          // samples per block
#define NT  256        // threads per block

// ---- shared memory float offsets ----
#define OFF_W1   0           // H1w  [12*25]           300
#define OFF_B1   300         // H1b  [12*64]           768
#define OFF_W2   1068        // H2w  padded oc-stride 201  12*201 = 2412
#define OFF_B2   3480        // H2b  [192]
#define OFF_WO   3672        // outw [300]
#define OFF_BO   3972        // outb [10] (pad 16)
#define OFF_B3   3988        // H3b  [30] (pad 32)
#define OFF_XIN  4020        // padded input  8 * 400 (20x20)
#define OFF_C1   7220        // padded conv1 out, ch-stride 149: 8 * 1788
#define OFF_C2   21524       // conv2 out 8 * 192
#define OFF_F1   23060       // fc1 out 8 * 32
#define OFF_OUT  23316       // fc2 out 8 * 10
#define SMEM_FLOATS 23396    // 93584 bytes

#define C1_CH_STRIDE 149     // 12x12 spatial (144) + 5 pad -> conflict-free banks
#define W2_OC_STRIDE 201     // 8*25 (200) + 1 pad       -> conflict-free banks
#define C1_PER_SAMPLE 1788   // 12 * 149

__global__ void __launch_bounds__(NT, 2) modernnet_kernel(
    const float* __restrict__ x,
    const float* __restrict__ H1w, const float* __restrict__ H1b,
    const float* __restrict__ H2w, const float* __restrict__ H2b,
    const float* __restrict__ H3w, const float* __restrict__ H3b,
    const float* __restrict__ outw, const float* __restrict__ outb,
    float* __restrict__ out, int B)
{
    extern __shared__ float sm[];
    const int tid  = threadIdx.x;
    const int warp = tid >> 5;
    const int lane = tid & 31;
    const int blockSample = blockIdx.x * SPB;

    float* sW1  = sm + OFF_W1;
    float* sB1  = sm + OFF_B1;
    float* sW2  = sm + OFF_W2;
    float* sB2  = sm + OFF_B2;
    float* sWo  = sm + OFF_WO;
    float* sBo  = sm + OFF_BO;
    float* sB3  = sm + OFF_B3;
    float* sXin = sm + OFF_XIN;
    float* sC1  = sm + OFF_C1;
    float* sC2  = sm + OFF_C2;
    float* sF1  = sm + OFF_F1;
    float* sOut = sm + OFF_OUT;

    // ---------- Phase 0: weights to smem + pad-fill (-1.0) ----------
    for (int i = tid; i < 300; i += NT) sW1[i] = H1w[i];
    for (int i = tid; i < 768; i += NT) sB1[i] = H1b[i];
    for (int i = tid; i < 2400; i += NT) {
        int oc = i / 200, r = i - oc * 200;
        sW2[oc * W2_OC_STRIDE + r] = H2w[i];
    }
    for (int i = tid; i < 192; i += NT) sB2[i] = H2b[i];
    for (int i = tid; i < 300; i += NT) sWo[i] = outw[i];
    if (tid < 10) sBo[tid] = outb[tid];
    if (tid < 30) sB3[tid] = H3b[tid];
    for (int i = tid; i < SPB * 400; i += NT) sXin[i] = -1.0f;
    for (int i = tid; i < SPB * C1_PER_SAMPLE; i += NT) sC1[i] = -1.0f;
    __syncthreads();

    // ---------- Phase 1: load inputs into padded 20x20 buffers ----------
    {
        const int nval = min(SPB * 256, (B - blockSample) * 256);
        const float* gx = x + (size_t)blockSample * 256;
        for (int i = tid; i < nval; i += NT) {
            int s = i >> 8;
            int p = i & 255;
            int ih = p >> 4, iw = p & 15;
            sXin[s * 400 + (ih + 2) * 20 + (iw + 2)] = gx[i];
        }
    }
    __syncthreads();

    // ---------- Phase 2: conv1 5x5 s2, 1->12 ch, per-position bias, relu ----------
    // warp = sample; thread: quad q (2x2 output pixels), channel group of 6
    {
        const float* xin = sXin + warp * 400;
        float* c1 = sC1 + warp * C1_PER_SAMPLE;
        const int q   = lane & 15;
        const int chg = lane >> 4;            // 0 or 1
        const int oh0 = (q >> 2) * 2;
        const int ow0 = (q & 3) * 2;

        float p[7][7];
        #pragma unroll
        for (int i = 0; i < 7; i++)
            #pragma unroll
            for (int j = 0; j < 7; j++)
                p[i][j] = xin[(2 * oh0 + i) * 20 + (2 * ow0 + j)];

        #pragma unroll
        for (int cc = 0; cc < 6; cc++) {
            const int c = chg * 6 + cc;
            const float* w = sW1 + c * 25;
            float a00 = 0.f, a01 = 0.f, a10 = 0.f, a11 = 0.f;
            #pragma unroll
            for (int ki = 0; ki < 5; ki++)
                #pragma unroll
                for (int kj = 0; kj < 5; kj++) {
                    const float wv = w[ki * 5 + kj];
                    a00 = fmaf(p[ki][kj],         wv, a00);
                    a01 = fmaf(p[ki][kj + 2],     wv, a01);
                    a10 = fmaf(p[ki + 2][kj],     wv, a10);
                    a11 = fmaf(p[ki + 2][kj + 2], wv, a11);
                }
            const float* b = sB1 + c * 64;
            float* o = c1 + c * C1_CH_STRIDE;
            o[(oh0 + 2) * 12 + (ow0 + 2)] = fmaxf(a00 + b[oh0 * 8 + ow0],           0.f);
            o[(oh0 + 2) * 12 + (ow0 + 3)] = fmaxf(a01 + b[oh0 * 8 + ow0 + 1],       0.f);
            o[(oh0 + 3) * 12 + (ow0 + 2)] = fmaxf(a10 + b[(oh0 + 1) * 8 + ow0],     0.f);
            o[(oh0 + 3) * 12 + (ow0 + 3)] = fmaxf(a11 + b[(oh0 + 1) * 8 + ow0 + 1], 0.f);
        }
    }
    __syncthreads();

    // ---------- Phase 3: grouped conv2 5x5 s2, (8 in -> 4 out) x 3, bias, relu ----------
    // thread (lane<24): oc = lane>>1, half = lane&1 (output rows {0,1} or {2,3})
    if (lane < 24) {
        const int oc   = lane >> 1;
        const int half = lane & 1;
        const int g    = oc >> 2;             // group 0,1,2
        const float* c1 = sC1 + warp * C1_PER_SAMPLE;
        const float* w  = sW2 + oc * W2_OC_STRIDE;

        float acc[2][4];
        #pragma unroll
        for (int r = 0; r < 2; r++)
            #pragma unroll
            for (int c = 0; c < 4; c++) acc[r][c] = 0.f;

        #pragma unroll
        for (int ic = 0; ic < 8; ic++) {
            // group 0: inch=ic; group 1: inch=ic+4; group 2: inch = ic<4 ? ic : ic+4
            const int inch = ic + ((g == 1) ? 4 : ((g == 2 && ic >= 4) ? 4 : 0));
            const float* ip = c1 + inch * C1_CH_STRIDE + half * 4 * 12;
            const float* wp = w + ic * 25;

            float p[7][11];
            #pragma unroll
            for (int i = 0; i < 7; i++)
                #pragma unroll
                for (int j = 0; j < 11; j++)
                    p[i][j] = ip[i * 12 + j];

            #pragma unroll
            for (int ki = 0; ki < 5; ki++)
                #pragma unroll
                for (int kj = 0; kj < 5; kj++) {
                    const float wv = wp[ki * 5 + kj];
                    #pragma unroll
                    for (int r = 0; r < 2; r++)
                        #pragma unroll
                        for (int c = 0; c < 4; c++)
                            acc[r][c] = fmaf(p[2 * r + ki][2 * c + kj], wv, acc[r][c]);
                }
        }

        float* c2 = sC2 + warp * 192;
        #pragma unroll
        for (int r = 0; r < 2; r++)
            #pragma unroll
            for (int c = 0; c < 4; c++) {
                const int orow = half * 2 + r;
                const int idx = oc * 16 + orow * 4 + c;
                c2[idx] = fmaxf(acc[r][c] + sB2[idx], 0.f);
            }
    }
    __syncthreads();

    // ---------- Phase 4: fc1 192->30, relu (H3w via L1-cached LDG) ----------
    if (lane < 30) {
        const float* a = sC2 + warp * 192;
        float acc = sB3[lane];
        #pragma unroll
        for (int k = 0; k < 192; k++)
            acc = fmaf(a[k], __ldg(&H3w[k * 30 + lane]), acc);
        sF1[warp * 32 + lane] = fmaxf(acc, 0.f);
    }
    __syncthreads();

    // ---------- Phase 5: fc2 30->10 ----------
    if (lane < 10) {
        const float* f = sF1 + warp * 32;
        float acc = sBo[lane];
        #pragma unroll
        for (int k = 0; k < 30; k++)
            acc = fmaf(f[k], sWo[k * 10 + lane], acc);
        sOut[warp * 10 + lane] = acc;
    }
    __syncthreads();

    // ---------- Phase 6: coalesced output store ----------
    {
        const int nval = min(SPB, B - blockSample) * 10;
        if (tid < nval)
            out[(size_t)blockSample * 10 + tid] = sOut[tid];
    }
}

extern "C" void kernel_launch(void* const* d_in, const int* in_sizes, int n_in,
                              void* d_out, int out_size) {
    const float* x    = (const float*)d_in[0];
    const float* H1w  = (const float*)d_in[1];
    const float* H1b  = (const float*)d_in[2];
    const float* H2w  = (const float*)d_in[3];
    const float* H2b  = (const float*)d_in[4];
    const float* H3w  = (const float*)d_in[5];
    const float* H3b  = (const float*)d_in[6];
    const float* outw = (const float*)d_in[7];
    const float* outb = (const float*)d_in[8];

    const int B = in_sizes[0] / 256;           // x is [B,1,16,16]
    const int blocks = (B + SPB - 1) / SPB;
    const size_t smem = SMEM_FLOATS * sizeof(float);

    cudaFuncSetAttribute(modernnet_kernel,
                         cudaFuncAttributeMaxDynamicSharedMemorySize, (int)smem);

    modernnet_kernel<<<blocks, NT, smem>>>(x, H1w, H1b, H2w, H2b,
                                           H3w, H3b, outw, outb,
                                           (float*)d_out, B);
}